// round 9
// baseline (speedup 1.0000x reference)
#include <cuda_runtime.h>

typedef unsigned long long u64;
#define DI static __device__ __forceinline__
DI u64 pk2(float lo, float hi){ u64 r; asm("mov.b64 %0,{%1,%2};":"=l"(r):"f"(lo),"f"(hi)); return r; }
DI void up2(u64 v, float&a, float&b){ asm("mov.b64 {%0,%1},%2;":"=f"(a),"=f"(b):"l"(v)); }
DI u64 fma2(u64 a,u64 b,u64 c){ u64 d; asm("fma.rn.f32x2 %0,%1,%2,%3;":"=l"(d):"l"(a),"l"(b),"l"(c)); return d; }

#define SS 1024
#define CS 768
#define NH 24

__device__ __align__(16) float g_emb[2*3*CS];
__device__ __align__(16) float g_bsn[2*SS*CS];
__device__ __align__(16) float g_q[2*SS*CS];
__device__ __align__(16) float g_k[2*SS*CS];
__device__ __align__(16) float g_v[2*SS*CS];
__device__ __align__(16) float g_attno[2*SS*CS];
__device__ __align__(16) float g_bias[NH*SS*SS];
__device__ __align__(16) float g_wzpf[128*NH];
__device__ float g_colsum[NH];
__device__ float g_consth[NH];

__global__ void k_prep(const float* __restrict__ wz, const float* __restrict__ lnw,
                       const float* __restrict__ lnb){
    int t = threadIdx.x; // 128
    float w = lnw[t];
    #pragma unroll
    for(int h=0;h<NH;h++) g_wzpf[t*NH+h] = w*wz[t*NH+h];
    if(t < NH){
        float cs=0.f, ch=0.f;
        for(int c=0;c<128;c++){ cs += lnw[c]*wz[c*NH+t]; ch += lnb[c]*wz[c*NH+t]; }
        g_colsum[t]=cs; g_consth[t]=ch;
    }
}

__global__ void k_emb(const float* __restrict__ tin, const float* __restrict__ wad,
                      const float* __restrict__ bad){
    __shared__ float st[CS];
    int b = blockIdx.y;
    for(int i=threadIdx.x;i<CS;i+=256){ float v=tin[b*CS+i]; st[i]=v/(1.f+__expf(-v)); }
    __syncthreads();
    int j = blockIdx.x*256 + threadIdx.x; // 9*256=2304
    float acc = bad[j];
    #pragma unroll 8
    for(int i=0;i<CS;i++) acc = fmaf(st[i], wad[i*2304+j], acc);
    g_emb[b*2304+j] = acc;
}

__global__ void k_bsnorm(const float* __restrict__ bs){
    int row = blockIdx.x, b = row>>10;
    const float* x = bs + row*CS;
    __shared__ float red[16];
    float v[3]; float s=0.f, ss=0.f;
    #pragma unroll
    for(int i=0;i<3;i++){ v[i]=x[threadIdx.x+i*256]; s+=v[i]; ss=fmaf(v[i],v[i],ss); }
    #pragma unroll
    for(int m=16;m;m>>=1){ s+=__shfl_xor_sync(~0u,s,m); ss+=__shfl_xor_sync(~0u,ss,m); }
    if((threadIdx.x&31)==0){ red[threadIdx.x>>5]=s; red[8+(threadIdx.x>>5)]=ss; }
    __syncthreads();
    float S=0.f, SSm=0.f;
    #pragma unroll
    for(int i=0;i<8;i++){ S+=red[i]; SSm+=red[8+i]; }
    float mu = S*(1.f/768.f);
    float rs = rsqrtf(SSm*(1.f/768.f)-mu*mu + 1e-5f);
    #pragma unroll
    for(int i=0;i<3;i++){
        int c = threadIdx.x+i*256;
        g_bsn[row*CS+c] = (v[i]-mu)*rs*(1.f+g_emb[b*2304+768+c])+g_emb[b*2304+c];
    }
}

// fused LN(z) + einsum + mask -> g_bias[h][i*1024+j]
__global__ void __launch_bounds__(128) k_bias(const float* __restrict__ z,
                                              const int* __restrict__ zm){
    __shared__ __align__(16) float sz[128*66];
    __shared__ __align__(16) ulonglong2 swzp[128*6];
    int t = threadIdx.x;
    int p0 = blockIdx.x*128;
    {   const float* wr = g_wzpf + t*NH;
        #pragma unroll
        for(int j2=0;j2<6;j2++){
            ulonglong2 e; e.x = pk2(wr[4*j2+0], wr[4*j2+1]); e.y = pk2(wr[4*j2+2], wr[4*j2+3]);
            swzp[t*6+j2]=e;
        }
    }
    u64 acc[12];
    #pragma unroll
    for(int j=0;j<12;j++) acc[j]=0ull;
    float s=0.f, ss=0.f;
    for(int ch=0; ch<2; ch++){
        __syncthreads();
        for(int li=t; li<2048; li+=128){
            int row = li>>4, q = li&15;
            float4 f = *(const float4*)(z + (p0+row)*128 + ch*64 + q*4);
            float2* d = (float2*)(sz + row*66 + q*4);
            d[0]=make_float2(f.x,f.y); d[1]=make_float2(f.z,f.w);
        }
        __syncthreads();
        const float* zr = sz + t*66;
        #pragma unroll 4
        for(int c=0;c<64;c++){
            float zv = zr[c];
            u64 zz = pk2(zv,zv);
            const ulonglong2* wr = swzp + (ch*64+c)*6;
            #pragma unroll
            for(int j2=0;j2<6;j2++){
                ulonglong2 wv = wr[j2];
                acc[2*j2]   = fma2(zz, wv.x, acc[2*j2]);
                acc[2*j2+1] = fma2(zz, wv.y, acc[2*j2+1]);
            }
            s += zv; ss = fmaf(zv,zv,ss);
        }
    }
    int p = p0 + t;
    float mu = s*(1.f/128.f);
    float rs = rsqrtf(ss*(1.f/128.f)-mu*mu + 1e-5f);
    float mb = (zm[p]>0) ? 0.f : -1e9f;
    #pragma unroll
    for(int j=0;j<12;j++){
        float d0,d1; up2(acc[j],d0,d1);
        g_bias[(2*j  )*1048576 + p] = rs*(d0-mu*g_colsum[2*j  ]) + g_consth[2*j  ] + mb;
        g_bias[(2*j+1)*1048576 + p] = rs*(d1-mu*g_colsum[2*j+1]) + g_consth[2*j+1] + mb;
    }
}

// C[2048x768] = A @ W ; asel 0:g_bsn 1:g_attno ; csel 0..2 -> q/k/v, 3 -> Cext (+b_o, *gate)
__global__ void __launch_bounds__(256) k_gemm(const float* __restrict__ W, float* __restrict__ Cext,
                                              const float* __restrict__ bo, int asel, int csel){
    __shared__ __align__(16) float as[16*130];
    __shared__ __align__(16) float bsm[16*64];
    const float* A = asel ? g_attno : g_bsn;
    float* C = (csel==0)?g_q : (csel==1)?g_k : (csel==2)?g_v : Cext;
    int t = threadIdx.x, tx = t&15, ty = t>>4;
    int m0 = blockIdx.y*128, n0 = blockIdx.x*64;
    u64 acc[8][2];
    #pragma unroll
    for(int r=0;r<8;r++){ acc[r][0]=0ull; acc[r][1]=0ull; }
    for(int k0=0;k0<768;k0+=16){
        __syncthreads();
        #pragma unroll
        for(int i=0;i<2;i++){
            int li = t + i*256; int m = li>>2, kq = li&3;
            float4 f = *(const float4*)(A + (m0+m)*768 + k0 + kq*4);
            as[(kq*4+0)*130+m]=f.x; as[(kq*4+1)*130+m]=f.y;
            as[(kq*4+2)*130+m]=f.z; as[(kq*4+3)*130+m]=f.w;
        }
        {   int k = t>>4, nq = t&15;
            *(float4*)(bsm + k*64 + nq*4) = *(const float4*)(W + (k0+k)*768 + n0 + nq*4);
        }
        __syncthreads();
        #pragma unroll
        for(int kk=0;kk<16;kk++){
            const float2* ap = (const float2*)(as + kk*130 + ty*8);
            ulonglong2 bb = *(const ulonglong2*)(bsm + kk*64 + tx*4);
            #pragma unroll
            for(int p=0;p<4;p++){
                float2 a2 = ap[p];
                u64 r0 = pk2(a2.x,a2.x), r1 = pk2(a2.y,a2.y);
                acc[2*p  ][0]=fma2(r0,bb.x,acc[2*p  ][0]); acc[2*p  ][1]=fma2(r0,bb.y,acc[2*p  ][1]);
                acc[2*p+1][0]=fma2(r1,bb.x,acc[2*p+1][0]); acc[2*p+1][1]=fma2(r1,bb.y,acc[2*p+1][1]);
            }
        }
    }
    #pragma unroll
    for(int r=0;r<8;r++){
        int m = m0 + ty*8 + r, n = n0 + tx*4;
        float o0,o1,o2,o3; up2(acc[r][0],o0,o1); up2(acc[r][1],o2,o3);
        if(csel==3){
            const float* g = g_emb + (m>>10)*2304 + 1536;
            o0=(o0+bo[n])*g[n]; o1=(o1+bo[n+1])*g[n+1]; o2=(o2+bo[n+2])*g[n+2]; o3=(o3+bo[n+3])*g[n+3];
        }
        *(float4*)(C + m*768 + n) = make_float4(o0,o1,o2,o3);
    }
}

__global__ void k_rms(const float* __restrict__ qw, const float* __restrict__ kw){
    int sel = blockIdx.y;
    float* data = sel ? g_k : g_q;
    const float* w = sel ? kw : qw;
    float scale = sel ? 1.f : 0.17677669529663687f; // 1/sqrt(32) folded into q
    int lane = threadIdx.x&31, wi = threadIdx.x>>5;
    int row = blockIdx.x*8 + wi; // (b,s,h) rows: 49152
    int addr = (row/24)*768 + (row%24)*32 + lane;
    float v = data[addr];
    float ss = v*v;
    #pragma unroll
    for(int m=16;m;m>>=1) ss += __shfl_xor_sync(~0u,ss,m);
    data[addr] = v * rsqrtf(ss*(1.f/32.f)+1e-5f) * w[lane] * scale;
}

__global__ void __launch_bounds__(256) k_attn(const float* __restrict__ beta){
    __shared__ __align__(16) float Qs[64*34];
    __shared__ __align__(16) float Kt[32*68];   // d-major
    __shared__ __align__(16) float Vs[64*34];
    __shared__ __align__(16) float Ps[64*68];
    int t=threadIdx.x, tx=t&15, ty=t>>4;
    int h=blockIdx.y, b=blockIdx.z, s0=blockIdx.x*64;
    const float* qb = g_q + (b*1024+s0)*768 + h*32;
    #pragma unroll
    for(int i=0;i<2;i++){
        int li=t+i*256, row=li>>3, e=li&7;
        float4 f = *(const float4*)(qb + row*768 + e*4);
        float2* d=(float2*)(Qs+row*34+e*4);
        d[0]=make_float2(f.x,f.y); d[1]=make_float2(f.z,f.w);
    }
    float m[4], l[4], O[4][2];
    #pragma unroll
    for(int ii=0;ii<4;ii++){ m[ii]=-1e30f; l[ii]=0.f; O[ii][0]=0.f; O[ii][1]=0.f; }
    const float* bias_h = g_bias + h*1048576 + s0*1024;
    const float* beta_b = beta  + b*1048576 + s0*1024;
    for(int kt=0;kt<16;kt++){
        int j0=kt*64;
        float S[4][4];
        #pragma unroll
        for(int ii=0;ii<4;ii++)
            #pragma unroll
            for(int jj=0;jj<4;jj++){
                int idx=(ty*4+ii)*1024 + j0+tx*4+jj;
                S[ii][jj]=bias_h[idx]+beta_b[idx];
            }
        const float* kb = g_k + (b*1024+j0)*768 + h*32;
        const float* vb = g_v + (b*1024+j0)*768 + h*32;
        float4 kf[2], vf[2];
        #pragma unroll
        for(int i=0;i<2;i++){
            int li=t+i*256, row=li>>3, e=li&7;
            kf[i]=*(const float4*)(kb+row*768+e*4);
            vf[i]=*(const float4*)(vb+row*768+e*4);
        }
        __syncthreads();  // previous tile's smem reads done
        #pragma unroll
        for(int i=0;i<2;i++){
            int li=t+i*256, row=li>>3, e=li&7;
            Kt[(e*4+0)*68+row]=kf[i].x; Kt[(e*4+1)*68+row]=kf[i].y;
            Kt[(e*4+2)*68+row]=kf[i].z; Kt[(e*4+3)*68+row]=kf[i].w;
            float2* dv=(float2*)(Vs+row*34+e*4);
            dv[0]=make_float2(vf[i].x,vf[i].y); dv[1]=make_float2(vf[i].z,vf[i].w);
        }
        __syncthreads();
        #pragma unroll 8
        for(int d=0;d<32;d++){
            float4 k4 = *(const float4*)(Kt + d*68 + tx*4);
            #pragma unroll
            for(int ii=0;ii<4;ii++){
                float qv = Qs[(ty*4+ii)*34+d];
                S[ii][0]=fmaf(qv,k4.x,S[ii][0]); S[ii][1]=fmaf(qv,k4.y,S[ii][1]);
                S[ii][2]=fmaf(qv,k4.z,S[ii][2]); S[ii][3]=fmaf(qv,k4.w,S[ii][3]);
            }
        }
        #pragma unroll
        for(int ii=0;ii<4;ii++){
            float mx = fmaxf(fmaxf(S[ii][0],S[ii][1]),fmaxf(S[ii][2],S[ii][3]));
            #pragma unroll
            for(int w=1;w<16;w<<=1) mx = fmaxf(mx, __shfl_xor_sync(~0u,mx,w));
            float mn = fmaxf(m[ii], mx);
            float sc = __expf(m[ii]-mn);
            float p0=__expf(S[ii][0]-mn), p1=__expf(S[ii][1]-mn);
            float p2=__expf(S[ii][2]-mn), p3=__expf(S[ii][3]-mn);
            *(float4*)(Ps + (ty*4+ii)*68 + tx*4) = make_float4(p0,p1,p2,p3);
            float rs = p0+p1+p2+p3;
            #pragma unroll
            for(int w=1;w<16;w<<=1) rs += __shfl_xor_sync(~0u,rs,w);
            l[ii] = l[ii]*sc + rs; m[ii] = mn;
            O[ii][0]*=sc; O[ii][1]*=sc;
        }
        __syncthreads();
        #pragma unroll 4
        for(int j4=0;j4<64;j4+=4){
            float2 vv0=*(const float2*)(Vs+(j4+0)*34+tx*2);
            float2 vv1=*(const float2*)(Vs+(j4+1)*34+tx*2);
            float2 vv2=*(const float2*)(Vs+(j4+2)*34+tx*2);
            float2 vv3=*(const float2*)(Vs+(j4+3)*34+tx*2);
            #pragma unroll
            for(int ii=0;ii<4;ii++){
                float4 p4 = *(const float4*)(Ps + (ty*4+ii)*68 + j4);
                O[ii][0] += p4.x*vv0.x + p4.y*vv1.x + p4.z*vv2.x + p4.w*vv3.x;
                O[ii][1] += p4.x*vv0.y + p4.y*vv1.y + p4.z*vv2.y + p4.w*vv3.y;
            }
        }
    }
    #pragma unroll
    for(int ii=0;ii<4;ii++){
        float inv = 1.f/l[ii];
        float* o = g_attno + (b*1024+s0+ty*4+ii)*768 + h*32 + tx*2;
        o[0]=O[ii][0]*inv; o[1]=O[ii][1]*inv;
    }
}

extern "C" void kernel_launch(void* const* d_in, const int* in_sizes, int n_in,
                              void* d_out, int out_size) {
    const float* bs   = (const float*)d_in[0];
    const float* z    = (const float*)d_in[1];
    const float* tt   = (const float*)d_in[2];
    const float* beta = (const float*)d_in[3];
    const int*   zm   = (const int*)  d_in[4];
    const float* wad  = (const float*)d_in[5];
    const float* bad  = (const float*)d_in[6];
    const float* lnzw = (const float*)d_in[7];
    const float* lnzb = (const float*)d_in[8];
    const float* wq   = (const float*)d_in[9];
    const float* wk   = (const float*)d_in[10];
    const float* wv   = (const float*)d_in[11];
    const float* wz   = (const float*)d_in[12];
    const float* rqw  = (const float*)d_in[13];
    const float* rkw  = (const float*)d_in[14];
    const float* wo   = (const float*)d_in[15];
    const float* bo   = (const float*)d_in[16];
    float* out = (float*)d_out;

    k_prep<<<1,128>>>(wz, lnzw, lnzb);
    k_emb<<<dim3(9,2),256>>>(tt, wad, bad);
    k_bsnorm<<<2048,256>>>(bs);
    k_bias<<<8192,128>>>(z, zm);
    k_gemm<<<dim3(12,16),256>>>(wq, nullptr, nullptr, 0, 0);
    k_gemm<<<dim3(12,16),256>>>(wk, nullptr, nullptr, 0, 1);
    k_gemm<<<dim3(12,16),256>>>(wv, nullptr, nullptr, 0, 2);
    k_rms<<<dim3(6144,2),256>>>(rqw, rkw);
    k_attn<<<dim3(16,24,2),256>>>(beta);
    k_gemm<<<dim3(12,16),256>>>(wo, out, bo, 1, 3);
}

// round 10
// speedup vs baseline: 1.0420x; 1.0420x over previous
#include <cuda_runtime.h>

typedef unsigned long long u64;
#define DI static __device__ __forceinline__
DI u64 pk2(float lo, float hi){ u64 r; asm("mov.b64 %0,{%1,%2};":"=l"(r):"f"(lo),"f"(hi)); return r; }
DI void up2(u64 v, float&a, float&b){ asm("mov.b64 {%0,%1},%2;":"=f"(a),"=f"(b):"l"(v)); }
DI u64 fma2(u64 a,u64 b,u64 c){ u64 d; asm("fma.rn.f32x2 %0,%1,%2,%3;":"=l"(d):"l"(a),"l"(b),"l"(c)); return d; }
DI void cpasync16(unsigned s, const void* g){ asm volatile("cp.async.cg.shared.global [%0], [%1], 16;" :: "r"(s), "l"(g)); }
DI void cpcommit(){ asm volatile("cp.async.commit_group;"); }
DI void cpwait0(){ asm volatile("cp.async.wait_group 0;"); }
DI void cpwait1(){ asm volatile("cp.async.wait_group 1;"); }

#define SS 1024
#define CS 768
#define NH 24

__device__ __align__(16) float g_emb[2*3*CS];
__device__ __align__(16) float g_bsn[2*SS*CS];
__device__ __align__(16) float g_q[2*SS*CS];
__device__ __align__(16) float g_k[2*SS*CS];
__device__ __align__(16) float g_v[2*SS*CS];
__device__ __align__(16) float g_attno[2*SS*CS];
__device__ __align__(16) float g_bias[NH*SS*SS];
__device__ __align__(16) float g_wzpf[128*NH];
__device__ float g_colsum[NH];
__device__ float g_consth[NH];

__global__ void k_prep(const float* __restrict__ wz, const float* __restrict__ lnw,
                       const float* __restrict__ lnb){
    int t = threadIdx.x; // 128
    float w = lnw[t];
    #pragma unroll
    for(int h=0;h<NH;h++) g_wzpf[t*NH+h] = w*wz[t*NH+h];
    if(t < NH){
        float cs=0.f, ch=0.f;
        for(int c=0;c<128;c++){ cs += lnw[c]*wz[c*NH+t]; ch += lnb[c]*wz[c*NH+t]; }
        g_colsum[t]=cs; g_consth[t]=ch;
    }
}

__global__ void k_emb(const float* __restrict__ tin, const float* __restrict__ wad,
                      const float* __restrict__ bad){
    __shared__ float st[CS];
    int b = blockIdx.y;
    for(int i=threadIdx.x;i<CS;i+=256){ float v=tin[b*CS+i]; st[i]=v/(1.f+__expf(-v)); }
    __syncthreads();
    int j = blockIdx.x*256 + threadIdx.x;
    float acc = bad[j];
    #pragma unroll 8
    for(int i=0;i<CS;i++) acc = fmaf(st[i], wad[i*2304+j], acc);
    g_emb[b*2304+j] = acc;
}

__global__ void k_bsnorm(const float* __restrict__ bs){
    int row = blockIdx.x, b = row>>10;
    const float* x = bs + row*CS;
    __shared__ float red[16];
    float v[3]; float s=0.f, ss=0.f;
    #pragma unroll
    for(int i=0;i<3;i++){ v[i]=x[threadIdx.x+i*256]; s+=v[i]; ss=fmaf(v[i],v[i],ss); }
    #pragma unroll
    for(int m=16;m;m>>=1){ s+=__shfl_xor_sync(~0u,s,m); ss+=__shfl_xor_sync(~0u,ss,m); }
    if((threadIdx.x&31)==0){ red[threadIdx.x>>5]=s; red[8+(threadIdx.x>>5)]=ss; }
    __syncthreads();
    float S=0.f, SSm=0.f;
    #pragma unroll
    for(int i=0;i<8;i++){ S+=red[i]; SSm+=red[8+i]; }
    float mu = S*(1.f/768.f);
    float rs = rsqrtf(SSm*(1.f/768.f)-mu*mu + 1e-5f);
    #pragma unroll
    for(int i=0;i<3;i++){
        int c = threadIdx.x+i*256;
        g_bsn[row*CS+c] = (v[i]-mu)*rs*(1.f+g_emb[b*2304+768+c])+g_emb[b*2304+c];
    }
}

// ---- k_bias v3: warp-tiled GEMM form. 512 rows/block, 8 warps.
// lane = hg*8+rg: owns rows {warp*64+rg+8j} x heads {hg*6..hg*6+5}
#define ZSTR 36
#define BUFSZ (512*ZSTR)
extern __shared__ __align__(16) unsigned char dynsm[];

__global__ void __launch_bounds__(256,1) k_bias(const float* __restrict__ z,
                                                const int* __restrict__ zm){
    u64* swzp = (u64*)dynsm;                       // 128c x 4hg x 4 u64 = 16KB
    float* zbuf = (float*)(dynsm + 16384);         // 2 x 512 x 36 floats
    unsigned zshm = (unsigned)__cvta_generic_to_shared(zbuf);
    int t = threadIdx.x;
    long long p0 = (long long)blockIdx.x * 512;
    // build packed wzp table
    for(int e=t; e<512; e+=256){
        int c = e>>2, hg = e&3;
        const float* w = g_wzpf + c*24 + hg*6;
        u64* dst = swzp + e*4;
        dst[0]=pk2(w[0],w[1]); dst[1]=pk2(w[2],w[3]); dst[2]=pk2(w[4],w[5]); dst[3]=0;
    }
    int lane = t&31, warp = t>>5;
    int rg = lane&7, hg = lane>>3;
    int rowBase = warp*64 + rg;

    u64 acc[8][3];
    float s[8], ss[8];
    #pragma unroll
    for(int j=0;j<8;j++){ acc[j][0]=0; acc[j][1]=0; acc[j][2]=0; s[j]=0.f; ss[j]=0.f; }

    // prefetch chunk 0 into buf 0
    {
        const float* src = z + p0*128;
        #pragma unroll
        for(int i=0;i<16;i++){
            int li = t + 256*i; int r = li>>3, q = li&7;
            cpasync16(zshm + (r*ZSTR + q*4)*4, src + (long long)r*128 + q*4);
        }
        cpcommit();
    }
    for(int ch=0; ch<4; ch++){
        if(ch < 3){
            int b = (ch+1)&1;
            const float* src = z + p0*128 + (ch+1)*32;
            #pragma unroll
            for(int i=0;i<16;i++){
                int li = t + 256*i; int r = li>>3, q = li&7;
                cpasync16(zshm + (b*BUFSZ + r*ZSTR + q*4)*4, src + (long long)r*128 + q*4);
            }
            cpcommit();
            cpwait1();
        } else {
            cpwait0();
        }
        __syncthreads();
        const float* zb = zbuf + (ch&1)*BUFSZ + rowBase*ZSTR;
        #pragma unroll
        for(int c4=0;c4<8;c4++){
            float4 zf[8];
            #pragma unroll
            for(int j=0;j<8;j++) zf[j] = *(const float4*)(zb + j*8*ZSTR + c4*4);
            #pragma unroll
            for(int cc=0;cc<4;cc++){
                int c = ch*32 + c4*4 + cc;
                const u64* w = swzp + (c*4 + hg)*4;
                ulonglong2 wp = *(const ulonglong2*)w;
                u64 w2 = w[2];
                #pragma unroll
                for(int j=0;j<8;j++){
                    float zv = (cc==0)?zf[j].x : (cc==1)?zf[j].y : (cc==2)?zf[j].z : zf[j].w;
                    u64 zz = pk2(zv,zv);
                    acc[j][0]=fma2(zz,wp.x,acc[j][0]);
                    acc[j][1]=fma2(zz,wp.y,acc[j][1]);
                    acc[j][2]=fma2(zz,w2 ,acc[j][2]);
                    s[j]+=zv; ss[j]=fmaf(zv,zv,ss[j]);
                }
            }
        }
        __syncthreads();
    }
    // epilogue
    float csl[6], chl[6];
    #pragma unroll
    for(int k=0;k<6;k++){ csl[k]=g_colsum[hg*6+k]; chl[k]=g_consth[hg*6+k]; }
    #pragma unroll
    for(int j=0;j<8;j++){
        long long p = p0 + rowBase + 8*j;
        float mu = s[j]*(1.f/128.f);
        float rs = rsqrtf(ss[j]*(1.f/128.f)-mu*mu + 1e-5f);
        float mb = (zm[p]>0) ? 0.f : -1e9f;
        #pragma unroll
        for(int k=0;k<3;k++){
            float d0,d1; up2(acc[j][k],d0,d1);
            int h0 = hg*6 + 2*k;
            g_bias[(long long)h0*1048576 + p]     = rs*(d0-mu*csl[2*k  ]) + chl[2*k  ] + mb;
            g_bias[(long long)(h0+1)*1048576 + p] = rs*(d1-mu*csl[2*k+1]) + chl[2*k+1] + mb;
        }
    }
}

// C[2048x768] = A @ W ; asel 0:g_bsn 1:g_attno ; csel 0..2 -> q/k/v, 3 -> Cext (+b_o, *gate)
__global__ void __launch_bounds__(256) k_gemm(const float* __restrict__ W, float* __restrict__ Cext,
                                              const float* __restrict__ bo, int asel, int csel){
    __shared__ __align__(16) float as[16*130];
    __shared__ __align__(16) float bsm[16*64];
    const float* A = asel ? g_attno : g_bsn;
    float* C = (csel==0)?g_q : (csel==1)?g_k : (csel==2)?g_v : Cext;
    int t = threadIdx.x, tx = t&15, ty = t>>4;
    int m0 = blockIdx.y*128, n0 = blockIdx.x*64;
    u64 acc[8][2];
    #pragma unroll
    for(int r=0;r<8;r++){ acc[r][0]=0ull; acc[r][1]=0ull; }
    for(int k0=0;k0<768;k0+=16){
        __syncthreads();
        #pragma unroll
        for(int i=0;i<2;i++){
            int li = t + i*256; int m = li>>2, kq = li&3;
            float4 f = *(const float4*)(A + (m0+m)*768 + k0 + kq*4);
            as[(kq*4+0)*130+m]=f.x; as[(kq*4+1)*130+m]=f.y;
            as[(kq*4+2)*130+m]=f.z; as[(kq*4+3)*130+m]=f.w;
        }
        {   int k = t>>4, nq = t&15;
            *(float4*)(bsm + k*64 + nq*4) = *(const float4*)(W + (k0+k)*768 + n0 + nq*4);
        }
        __syncthreads();
        #pragma unroll
        for(int kk=0;kk<16;kk++){
            const float2* ap = (const float2*)(as + kk*130 + ty*8);
            ulonglong2 bb = *(const ulonglong2*)(bsm + kk*64 + tx*4);
            #pragma unroll
            for(int p=0;p<4;p++){
                float2 a2 = ap[p];
                u64 r0 = pk2(a2.x,a2.x), r1 = pk2(a2.y,a2.y);
                acc[2*p  ][0]=fma2(r0,bb.x,acc[2*p  ][0]); acc[2*p  ][1]=fma2(r0,bb.y,acc[2*p  ][1]);
                acc[2*p+1][0]=fma2(r1,bb.x,acc[2*p+1][0]); acc[2*p+1][1]=fma2(r1,bb.y,acc[2*p+1][1]);
            }
        }
    }
    #pragma unroll
    for(int r=0;r<8;r++){
        int m = m0 + ty*8 + r, n = n0 + tx*4;
        float o0,o1,o2,o3; up2(acc[r][0],o0,o1); up2(acc[r][1],o2,o3);
        if(csel==3){
            const float* g = g_emb + (m>>10)*2304 + 1536;
            o0=(o0+bo[n])*g[n]; o1=(o1+bo[n+1])*g[n+1]; o2=(o2+bo[n+2])*g[n+2]; o3=(o3+bo[n+3])*g[n+3];
        }
        *(float4*)(C + m*768 + n) = make_float4(o0,o1,o2,o3);
    }
}

__global__ void k_rms(const float* __restrict__ qw, const float* __restrict__ kw){
    int sel = blockIdx.y;
    float* data = sel ? g_k : g_q;
    const float* w = sel ? kw : qw;
    float scale = sel ? 1.f : 0.17677669529663687f;
    int lane = threadIdx.x&31, wi = threadIdx.x>>5;
    int row = blockIdx.x*8 + wi;
    int addr = (row/24)*768 + (row%24)*32 + lane;
    float v = data[addr];
    float ss = v*v;
    #pragma unroll
    for(int m=16;m;m>>=1) ss += __shfl_xor_sync(~0u,ss,m);
    data[addr] = v * rsqrtf(ss*(1.f/32.f)+1e-5f) * w[lane] * scale;
}

__global__ void __launch_bounds__(256) k_attn(const float* __restrict__ beta){
    __shared__ __align__(16) float Qs[64*34];
    __shared__ __align__(16) float Kt[32*68];
    __shared__ __align__(16) float Vs[64*34];
    __shared__ __align__(16) float Ps[64*68];
    int t=threadIdx.x, tx=t&15, ty=t>>4;
    int h=blockIdx.y, b=blockIdx.z, s0=blockIdx.x*64;
    const float* qb = g_q + (b*1024+s0)*768 + h*32;
    #pragma unroll
    for(int i=0;i<2;i++){
        int li=t+i*256, row=li>>3, e=li&7;
        float4 f = *(const float4*)(qb + row*768 + e*4);
        float2* d=(float2*)(Qs+row*34+e*4);
        d[0]=make_float2(f.x,f.y); d[1]=make_float2(f.z,f.w);
    }
    float m[4], l[4], O[4][2];
    #pragma unroll
    for(int ii=0;ii<4;ii++){ m[ii]=-1e30f; l[ii]=0.f; O[ii][0]=0.f; O[ii][1]=0.f; }
    const float* bias_h = g_bias + (long long)h*1048576 + s0*1024;
    const float* beta_b = beta  + (long long)b*1048576 + s0*1024;
    for(int kt=0;kt<16;kt++){
        int j0=kt*64;
        float S[4][4];
        #pragma unroll
        for(int ii=0;ii<4;ii++)
            #pragma unroll
            for(int jj=0;jj<4;jj++){
                int idx=(ty*4+ii)*1024 + j0+tx*4+jj;
                S[ii][jj]=bias_h[idx]+beta_b[idx];
            }
        const float* kb = g_k + (b*1024+j0)*768 + h*32;
        const float* vb = g_v + (b*1024+j0)*768 + h*32;
        float4 kf[2], vf[2];
        #pragma unroll
        for(int i=0;i<2;i++){
            int li=t+i*256, row=li>>3, e=li&7;
            kf[i]=*(const float4*)(kb+row*768+e*4);
            vf[i]=*(const float4*)(vb+row*768+e*4);
        }
        __syncthreads();
        #pragma unroll
        for(int i=0;i<2;i++){
            int li=t+i*256, row=li>>3, e=li&7;
            Kt[(e*4+0)*68+row]=kf[i].x; Kt[(e*4+1)*68+row]=kf[i].y;
            Kt[(e*4+2)*68+row]=kf[i].z; Kt[(e*4+3)*68+row]=kf[i].w;
            float2* dv=(float2*)(Vs+row*34+e*4);
            dv[0]=make_float2(vf[i].x,vf[i].y); dv[1]=make_float2(vf[i].z,vf[i].w);
        }
        __syncthreads();
        #pragma unroll 8
        for(int d=0;d<32;d++){
            float4 k4 = *(const float4*)(Kt + d*68 + tx*4);
            #pragma unroll
            for(int ii=0;ii<4;ii++){
                float qv = Qs[(ty*4+ii)*34+d];
                S[ii][0]=fmaf(qv,k4.x,S[ii][0]); S[ii][1]=fmaf(qv,k4.y,S[ii][1]);
                S[ii][2]=fmaf(qv,k4.z,S[ii][2]); S[ii][3]=fmaf(qv,k4.w,S[ii][3]);
            }
        }
        #pragma unroll
        for(int ii=0;ii<4;ii++){
            float mx = fmaxf(fmaxf(S[ii][0],S[ii][1]),fmaxf(S[ii][2],S[ii][3]));
            #pragma unroll
            for(int w=1;w<16;w<<=1) mx = fmaxf(mx, __shfl_xor_sync(~0u,mx,w));
            float mn = fmaxf(m[ii], mx);
            float sc = __expf(m[ii]-mn);
            float p0=__expf(S[ii][0]-mn), p1=__expf(S[ii][1]-mn);
            float p2=__expf(S[ii][2]-mn), p3=__expf(S[ii][3]-mn);
            *(float4*)(Ps + (ty*4+ii)*68 + tx*4) = make_float4(p0,p1,p2,p3);
            float rs = p0+p1+p2+p3;
            #pragma unroll
            for(int w=1;w<16;w<<=1) rs += __shfl_xor_sync(~0u,rs,w);
            l[ii] = l[ii]*sc + rs; m[ii] = mn;
            O[ii][0]*=sc; O[ii][1]*=sc;
        }
        __syncthreads();
        #pragma unroll 4
        for(int j4=0;j4<64;j4+=4){
            float2 vv0=*(const float2*)(Vs+(j4+0)*34+tx*2);
            float2 vv1=*(const float2*)(Vs+(j4+1)*34+tx*2);
            float2 vv2=*(const float2*)(Vs+(j4+2)*34+tx*2);
            float2 vv3=*(const float2*)(Vs+(j4+3)*34+tx*2);
            #pragma unroll
            for(int ii=0;ii<4;ii++){
                float4 p4 = *(const float4*)(Ps + (ty*4+ii)*68 + j4);
                O[ii][0] += p4.x*vv0.x + p4.y*vv1.x + p4.z*vv2.x + p4.w*vv3.x;
                O[ii][1] += p4.x*vv0.y + p4.y*vv1.y + p4.z*vv2.y + p4.w*vv3.y;
            }
        }
    }
    #pragma unroll
    for(int ii=0;ii<4;ii++){
        float inv = 1.f/l[ii];
        float* o = g_attno + (b*1024+s0+ty*4+ii)*768 + h*32 + tx*2;
        o[0]=O[ii][0]*inv; o[1]=O[ii][1]*inv;
    }
}

extern "C" void kernel_launch(void* const* d_in, const int* in_sizes, int n_in,
                              void* d_out, int out_size) {
    const float* bs   = (const float*)d_in[0];
    const float* z    = (const float*)d_in[1];
    const float* tt   = (const float*)d_in[2];
    const float* beta = (const float*)d_in[3];
    const int*   zm   = (const int*)  d_in[4];
    const float* wad  = (const float*)d_in[5];
    const float* bad  = (const float*)d_in[6];
    const float* lnzw = (const float*)d_in[7];
    const float* lnzb = (const float*)d_in[8];
    const float* wq   = (const float*)d_in[9];
    const float* wk   = (const float*)d_in[10];
    const float* wv   = (const float*)d_in[11];
    const float* wz   = (const float*)d_in[12];
    const float* rqw  = (const float*)d_in[13];
    const float* rkw  = (const float*)d_in[14];
    const float* wo   = (const float*)d_in[15];
    const float* bo   = (const float*)d_in[16];
    float* out = (float*)d_out;

    cudaFuncSetAttribute(k_bias, cudaFuncAttributeMaxDynamicSharedMemorySize, 16384 + 2*BUFSZ*4);

    k_prep<<<1,128>>>(wz, lnzw, lnzb);
    k_emb<<<dim3(9,2),256>>>(tt, wad, bad);
    k_bsnorm<<<2048,256>>>(bs);
    k_bias<<<2048,256, 16384 + 2*BUFSZ*4>>>(z, zm);
    k_gemm<<<dim3(12,16),256>>>(wq, nullptr, nullptr, 0, 0);
    k_gemm<<<dim3(12,16),256>>>(wk, nullptr, nullptr, 0, 1);
    k_gemm<<<dim3(12,16),256>>>(wv, nullptr, nullptr, 0, 2);
    k_rms<<<dim3(6144,2),256>>>(rqw, rkw);
    k_attn<<<dim3(16,24,2),256>>>(beta);
    k_gemm<<<dim3(12,16),256>>>(wo, out, bo, 1, 3);
}

// round 11
// speedup vs baseline: 1.0466x; 1.0044x over previous
#include <cuda_runtime.h>

typedef unsigned long long u64;
#define DI static __device__ __forceinline__
DI u64 pk2(float lo, float hi){ u64 r; asm("mov.b64 %0,{%1,%2};":"=l"(r):"f"(lo),"f"(hi)); return r; }
DI void up2(u64 v, float&a, float&b){ asm("mov.b64 {%0,%1},%2;":"=f"(a),"=f"(b):"l"(v)); }
DI u64 fma2(u64 a,u64 b,u64 c){ u64 d; asm("fma.rn.f32x2 %0,%1,%2,%3;":"=l"(d):"l"(a),"l"(b),"l"(c)); return d; }
DI u64 mul2(u64 a,u64 b){ u64 d; asm("mul.rn.f32x2 %0,%1,%2;":"=l"(d):"l"(a),"l"(b)); return d; }
DI void cpasync16(unsigned s, const void* g){ asm volatile("cp.async.cg.shared.global [%0], [%1], 16;" :: "r"(s), "l"(g)); }
DI void cpcommit(){ asm volatile("cp.async.commit_group;"); }
DI void cpwait0(){ asm volatile("cp.async.wait_group 0;"); }
DI void cpwait1(){ asm volatile("cp.async.wait_group 1;"); }

#define SS 1024
#define CS 768
#define NH 24

__device__ __align__(16) float g_emb[2*3*CS];
__device__ __align__(16) float g_bsn[2*SS*CS];
__device__ __align__(16) float g_q[2*SS*CS];
__device__ __align__(16) float g_k[2*SS*CS];
__device__ __align__(16) float g_v[2*SS*CS];
__device__ __align__(16) float g_attno[2*SS*CS];
__device__ __align__(16) float g_bias[NH*SS*SS];
__device__ __align__(16) float g_wzpf[128*NH];
__device__ float g_colsum[NH];
__device__ float g_consth[NH];

__global__ void k_prep(const float* __restrict__ wz, const float* __restrict__ lnw,
                       const float* __restrict__ lnb){
    int t = threadIdx.x; // 128
    float w = lnw[t];
    #pragma unroll
    for(int h=0;h<NH;h++) g_wzpf[t*NH+h] = w*wz[t*NH+h];
    if(t < NH){
        float cs=0.f, ch=0.f;
        for(int c=0;c<128;c++){ cs += lnw[c]*wz[c*NH+t]; ch += lnb[c]*wz[c*NH+t]; }
        g_colsum[t]=cs; g_consth[t]=ch;
    }
}

__global__ void k_emb(const float* __restrict__ tin, const float* __restrict__ wad,
                      const float* __restrict__ bad){
    __shared__ float st[CS];
    int b = blockIdx.y;
    for(int i=threadIdx.x;i<CS;i+=256){ float v=tin[b*CS+i]; st[i]=v/(1.f+__expf(-v)); }
    __syncthreads();
    int j = blockIdx.x*256 + threadIdx.x;
    float acc = bad[j];
    #pragma unroll 8
    for(int i=0;i<CS;i++) acc = fmaf(st[i], wad[i*2304+j], acc);
    g_emb[b*2304+j] = acc;
}

__global__ void k_bsnorm(const float* __restrict__ bs){
    int row = blockIdx.x, b = row>>10;
    const float* x = bs + row*CS;
    __shared__ float red[16];
    float v[3]; float s=0.f, ss=0.f;
    #pragma unroll
    for(int i=0;i<3;i++){ v[i]=x[threadIdx.x+i*256]; s+=v[i]; ss=fmaf(v[i],v[i],ss); }
    #pragma unroll
    for(int m=16;m;m>>=1){ s+=__shfl_xor_sync(~0u,s,m); ss+=__shfl_xor_sync(~0u,ss,m); }
    if((threadIdx.x&31)==0){ red[threadIdx.x>>5]=s; red[8+(threadIdx.x>>5)]=ss; }
    __syncthreads();
    float S=0.f, SSm=0.f;
    #pragma unroll
    for(int i=0;i<8;i++){ S+=red[i]; SSm+=red[8+i]; }
    float mu = S*(1.f/768.f);
    float rs = rsqrtf(SSm*(1.f/768.f)-mu*mu + 1e-5f);
    #pragma unroll
    for(int i=0;i<3;i++){
        int c = threadIdx.x+i*256;
        g_bsn[row*CS+c] = (v[i]-mu)*rs*(1.f+g_emb[b*2304+768+c])+g_emb[b*2304+c];
    }
}

// ---- k_bias v4: 512 threads, 16 warps. warp owns 32 rows; lane rg=lane&7 owns
// rows rg+8j (j<4), hg=lane>>3 owns heads hg*6..hg*6+5.
#define ZSTR 36
#define BUFSZ (512*ZSTR)
extern __shared__ __align__(16) unsigned char dynsm[];

__global__ void __launch_bounds__(512,1) k_bias(const float* __restrict__ z,
                                                const int* __restrict__ zm){
    u64* swzp = (u64*)dynsm;                       // 128c x 4hg x 4 u64 = 16KB
    float* zbuf = (float*)(dynsm + 16384);         // 2 x 512 x 36 floats
    unsigned zshm = (unsigned)__cvta_generic_to_shared(zbuf);
    int t = threadIdx.x;
    long long p0 = (long long)blockIdx.x * 512;
    {   // one table entry per thread
        int c = t>>2, hg = t&3;
        const float* w = g_wzpf + c*24 + hg*6;
        u64* dst = swzp + t*4;
        dst[0]=pk2(w[0],w[1]); dst[1]=pk2(w[2],w[3]); dst[2]=pk2(w[4],w[5]); dst[3]=0;
    }
    int lane = t&31, warp = t>>5;
    int rg = lane&7, hg = lane>>3;
    int rowBase = warp*32 + rg;

    u64 acc[4][3];
    float s[4], ss[4];
    #pragma unroll
    for(int j=0;j<4;j++){ acc[j][0]=0; acc[j][1]=0; acc[j][2]=0; s[j]=0.f; ss[j]=0.f; }

    {   // prefetch chunk 0 into buf 0
        const float* src = z + p0*128;
        #pragma unroll
        for(int i=0;i<8;i++){
            int li = t + 512*i; int r = li>>3, q = li&7;
            cpasync16(zshm + (r*ZSTR + q*4)*4, src + (long long)r*128 + q*4);
        }
        cpcommit();
    }
    for(int ch=0; ch<4; ch++){
        if(ch < 3){
            int b = (ch+1)&1;
            const float* src = z + p0*128 + (ch+1)*32;
            #pragma unroll
            for(int i=0;i<8;i++){
                int li = t + 512*i; int r = li>>3, q = li&7;
                cpasync16(zshm + (b*BUFSZ + r*ZSTR + q*4)*4, src + (long long)r*128 + q*4);
            }
            cpcommit();
            cpwait1();
        } else {
            cpwait0();
        }
        __syncthreads();
        const float* zb = zbuf + (ch&1)*BUFSZ + rowBase*ZSTR;
        #pragma unroll
        for(int c4=0;c4<8;c4++){
            float4 zf[4];
            #pragma unroll
            for(int j=0;j<4;j++) zf[j] = *(const float4*)(zb + j*8*ZSTR + c4*4);
            #pragma unroll
            for(int cc=0;cc<4;cc++){
                int c = ch*32 + c4*4 + cc;
                const u64* w = swzp + (c*4 + hg)*4;
                ulonglong2 wp = *(const ulonglong2*)w;
                u64 w2 = w[2];
                #pragma unroll
                for(int j=0;j<4;j++){
                    float zv = (cc==0)?zf[j].x : (cc==1)?zf[j].y : (cc==2)?zf[j].z : zf[j].w;
                    u64 zz = pk2(zv,zv);
                    acc[j][0]=fma2(zz,wp.x,acc[j][0]);
                    acc[j][1]=fma2(zz,wp.y,acc[j][1]);
                    acc[j][2]=fma2(zz,w2 ,acc[j][2]);
                    s[j]+=zv; ss[j]=fmaf(zv,zv,ss[j]);
                }
            }
        }
        __syncthreads();
    }
    float csl[6], chl[6];
    #pragma unroll
    for(int k=0;k<6;k++){ csl[k]=g_colsum[hg*6+k]; chl[k]=g_consth[hg*6+k]; }
    #pragma unroll
    for(int j=0;j<4;j++){
        long long p = p0 + rowBase + 8*j;
        float mu = s[j]*(1.f/128.f);
        float rs = rsqrtf(ss[j]*(1.f/128.f)-mu*mu + 1e-5f);
        float mb = (zm[p]>0) ? 0.f : -1e9f;
        #pragma unroll
        for(int k=0;k<3;k++){
            float d0,d1; up2(acc[j][k],d0,d1);
            int h0 = hg*6 + 2*k;
            g_bias[(long long)h0*1048576 + p]     = rs*(d0-mu*csl[2*k  ]) + chl[2*k  ] + mb;
            g_bias[(long long)(h0+1)*1048576 + p] = rs*(d1-mu*csl[2*k+1]) + chl[2*k+1] + mb;
        }
    }
}

// C[2048x768] = A @ W ; asel 0:g_bsn 1:g_attno ; csel 0..2 -> q/k/v, 3 -> Cext (+b_o, *gate)
__global__ void __launch_bounds__(256) k_gemm(const float* __restrict__ W, float* __restrict__ Cext,
                                              const float* __restrict__ bo, int asel, int csel){
    __shared__ __align__(16) float as[16*130];
    __shared__ __align__(16) float bsm[16*64];
    const float* A = asel ? g_attno : g_bsn;
    float* C = (csel==0)?g_q : (csel==1)?g_k : (csel==2)?g_v : Cext;
    int t = threadIdx.x, tx = t&15, ty = t>>4;
    int m0 = blockIdx.y*128, n0 = blockIdx.x*64;
    u64 acc[8][2];
    #pragma unroll
    for(int r=0;r<8;r++){ acc[r][0]=0ull; acc[r][1]=0ull; }
    for(int k0=0;k0<768;k0+=16){
        __syncthreads();
        #pragma unroll
        for(int i=0;i<2;i++){
            int li = t + i*256; int m = li>>2, kq = li&3;
            float4 f = *(const float4*)(A + (m0+m)*768 + k0 + kq*4);
            as[(kq*4+0)*130+m]=f.x; as[(kq*4+1)*130+m]=f.y;
            as[(kq*4+2)*130+m]=f.z; as[(kq*4+3)*130+m]=f.w;
        }
        {   int k = t>>4, nq = t&15;
            *(float4*)(bsm + k*64 + nq*4) = *(const float4*)(W + (k0+k)*768 + n0 + nq*4);
        }
        __syncthreads();
        #pragma unroll
        for(int kk=0;kk<16;kk++){
            const float2* ap = (const float2*)(as + kk*130 + ty*8);
            ulonglong2 bb = *(const ulonglong2*)(bsm + kk*64 + tx*4);
            #pragma unroll
            for(int p=0;p<4;p++){
                float2 a2 = ap[p];
                u64 r0 = pk2(a2.x,a2.x), r1 = pk2(a2.y,a2.y);
                acc[2*p  ][0]=fma2(r0,bb.x,acc[2*p  ][0]); acc[2*p  ][1]=fma2(r0,bb.y,acc[2*p  ][1]);
                acc[2*p+1][0]=fma2(r1,bb.x,acc[2*p+1][0]); acc[2*p+1][1]=fma2(r1,bb.y,acc[2*p+1][1]);
            }
        }
    }
    #pragma unroll
    for(int r=0;r<8;r++){
        int m = m0 + ty*8 + r, n = n0 + tx*4;
        float o0,o1,o2,o3; up2(acc[r][0],o0,o1); up2(acc[r][1],o2,o3);
        if(csel==3){
            const float* g = g_emb + (m>>10)*2304 + 1536;
            o0=(o0+bo[n])*g[n]; o1=(o1+bo[n+1])*g[n+1]; o2=(o2+bo[n+2])*g[n+2]; o3=(o3+bo[n+3])*g[n+3];
        }
        *(float4*)(C + m*768 + n) = make_float4(o0,o1,o2,o3);
    }
}

__global__ void k_rms(const float* __restrict__ qw, const float* __restrict__ kw){
    int sel = blockIdx.y;
    float* data = sel ? g_k : g_q;
    const float* w = sel ? kw : qw;
    float scale = sel ? 1.f : 0.17677669529663687f;
    int lane = threadIdx.x&31, wi = threadIdx.x>>5;
    int row = blockIdx.x*8 + wi;
    int addr = (row/24)*768 + (row%24)*32 + lane;
    float v = data[addr];
    float ss = v*v;
    #pragma unroll
    for(int m=16;m;m>>=1) ss += __shfl_xor_sync(~0u,ss,m);
    data[addr] = v * rsqrtf(ss*(1.f/32.f)+1e-5f) * w[lane] * scale;
}

__global__ void __launch_bounds__(256) k_attn(const float* __restrict__ beta){
    __shared__ __align__(16) float Qs[64*34];
    __shared__ __align__(16) float Kt[32*68];
    __shared__ __align__(16) float Vt[32*68];
    __shared__ __align__(16) float Ps[64*68];
    int t=threadIdx.x, tx=t&15, ty=t>>4;
    int h=blockIdx.y, b=blockIdx.z, s0=blockIdx.x*64;
    const float* qb = g_q + (b*1024+s0)*768 + h*32;
    #pragma unroll
    for(int i=0;i<2;i++){
        int li=t+i*256, row=li>>3, e=li&7;
        float4 f = *(const float4*)(qb + row*768 + e*4);
        float2* d=(float2*)(Qs+row*34+e*4);
        d[0]=make_float2(f.x,f.y); d[1]=make_float2(f.z,f.w);
    }
    float m[4], l[4]; u64 acc[4][2];
    #pragma unroll
    for(int ii=0;ii<4;ii++){ m[ii]=-1e30f; l[ii]=0.f; acc[ii][0]=0ull; acc[ii][1]=0ull; }
    const float* bias_h = g_bias + (long long)h*1048576 + s0*1024;
    const float* beta_b = beta  + (long long)b*1048576 + s0*1024;
    for(int kt=0;kt<16;kt++){
        int j0=kt*64;
        u64 S2[4][2];
        #pragma unroll
        for(int ii=0;ii<4;ii++){
            int idx=(ty*4+ii)*1024 + j0 + tx*4;
            float4 bb = *(const float4*)(bias_h + idx);
            float4 be = *(const float4*)(beta_b + idx);
            S2[ii][0]=pk2(bb.x+be.x, bb.y+be.y);
            S2[ii][1]=pk2(bb.z+be.z, bb.w+be.w);
        }
        const float* kb = g_k + (b*1024+j0)*768 + h*32;
        const float* vb = g_v + (b*1024+j0)*768 + h*32;
        float4 kf[2], vf[2];
        #pragma unroll
        for(int i=0;i<2;i++){
            int li=t+i*256, row=li>>3, e=li&7;
            kf[i]=*(const float4*)(kb+row*768+e*4);
            vf[i]=*(const float4*)(vb+row*768+e*4);
        }
        __syncthreads();
        #pragma unroll
        for(int i=0;i<2;i++){
            int li=t+i*256, row=li>>3, e=li&7;
            Kt[(e*4+0)*68+row]=kf[i].x; Kt[(e*4+1)*68+row]=kf[i].y;
            Kt[(e*4+2)*68+row]=kf[i].z; Kt[(e*4+3)*68+row]=kf[i].w;
            Vt[(e*4+0)*68+row]=vf[i].x; Vt[(e*4+1)*68+row]=vf[i].y;
            Vt[(e*4+2)*68+row]=vf[i].z; Vt[(e*4+3)*68+row]=vf[i].w;
        }
        __syncthreads();
        #pragma unroll 8
        for(int d=0;d<32;d++){
            ulonglong2 kk = *(const ulonglong2*)(Kt + d*68 + tx*4);
            #pragma unroll
            for(int ii=0;ii<4;ii++){
                float qv = Qs[(ty*4+ii)*34+d];
                u64 qq = pk2(qv,qv);
                S2[ii][0]=fma2(qq,kk.x,S2[ii][0]);
                S2[ii][1]=fma2(qq,kk.y,S2[ii][1]);
            }
        }
        #pragma unroll
        for(int ii=0;ii<4;ii++){
            float sv0,sv1,sv2,sv3;
            up2(S2[ii][0],sv0,sv1); up2(S2[ii][1],sv2,sv3);
            float mx = fmaxf(fmaxf(sv0,sv1),fmaxf(sv2,sv3));
            #pragma unroll
            for(int w=1;w<16;w<<=1) mx = fmaxf(mx, __shfl_xor_sync(~0u,mx,w));
            float mn = fmaxf(m[ii], mx);
            float sc = __expf(m[ii]-mn);
            float p0=__expf(sv0-mn), p1=__expf(sv1-mn);
            float p2=__expf(sv2-mn), p3=__expf(sv3-mn);
            *(float4*)(Ps + (ty*4+ii)*68 + tx*4) = make_float4(p0,p1,p2,p3);
            float rs = p0+p1+p2+p3;
            #pragma unroll
            for(int w=1;w<16;w<<=1) rs += __shfl_xor_sync(~0u,rs,w);
            l[ii] = l[ii]*sc + rs; m[ii] = mn;
            u64 scp = pk2(sc,sc);
            acc[ii][0]=mul2(acc[ii][0],scp); acc[ii][1]=mul2(acc[ii][1],scp);
        }
        __syncthreads();
        #pragma unroll 4
        for(int j4=0;j4<64;j4+=4){
            ulonglong2 v0 = *(const ulonglong2*)(Vt + tx*68 + j4);
            ulonglong2 v1 = *(const ulonglong2*)(Vt + (tx+16)*68 + j4);
            #pragma unroll
            for(int ii=0;ii<4;ii++){
                ulonglong2 pp = *(const ulonglong2*)(Ps + (ty*4+ii)*68 + j4);
                acc[ii][0]=fma2(pp.x, v0.x, acc[ii][0]);
                acc[ii][0]=fma2(pp.y, v0.y, acc[ii][0]);
                acc[ii][1]=fma2(pp.x, v1.x, acc[ii][1]);
                acc[ii][1]=fma2(pp.y, v1.y, acc[ii][1]);
            }
        }
    }
    #pragma unroll
    for(int ii=0;ii<4;ii++){
        float inv = 1.f/l[ii];
        float a0,a1,b0,b1;
        up2(acc[ii][0],a0,a1); up2(acc[ii][1],b0,b1);
        float* o = g_attno + (b*1024+s0+ty*4+ii)*768 + h*32;
        o[tx]    = (a0+a1)*inv;
        o[tx+16] = (b0+b1)*inv;
    }
}

extern "C" void kernel_launch(void* const* d_in, const int* in_sizes, int n_in,
                              void* d_out, int out_size) {
    const float* bs   = (const float*)d_in[0];
    const float* z    = (const float*)d_in[1];
    const float* tt   = (const float*)d_in[2];
    const float* beta = (const float*)d_in[3];
    const int*   zm   = (const int*)  d_in[4];
    const float* wad  = (const float*)d_in[5];
    const float* bad  = (const float*)d_in[6];
    const float* lnzw = (const float*)d_in[7];
    const float* lnzb = (const float*)d_in[8];
    const float* wq   = (const float*)d_in[9];
    const float* wk   = (const float*)d_in[10];
    const float* wv   = (const float*)d_in[11];
    const float* wz   = (const float*)d_in[12];
    const float* rqw  = (const float*)d_in[13];
    const float* rkw  = (const float*)d_in[14];
    const float* wo   = (const float*)d_in[15];
    const float* bo   = (const float*)d_in[16];
    float* out = (float*)d_out;

    cudaFuncSetAttribute(k_bias, cudaFuncAttributeMaxDynamicSharedMemorySize, 16384 + 2*BUFSZ*4);

    k_prep<<<1,128>>>(wz, lnzw, lnzb);
    k_emb<<<dim3(9,2),256>>>(tt, wad, bad);
    k_bsnorm<<<2048,256>>>(bs);
    k_bias<<<2048,512, 16384 + 2*BUFSZ*4>>>(z, zm);
    k_gemm<<<dim3(12,16),256>>>(wq, nullptr, nullptr, 0, 0);
    k_gemm<<<dim3(12,16),256>>>(wk, nullptr, nullptr, 0, 1);
    k_gemm<<<dim3(12,16),256>>>(wv, nullptr, nullptr, 0, 2);
    k_rms<<<dim3(6144,2),256>>>(rqw, rkw);
    k_attn<<<dim3(16,24,2),256>>>(beta);
    k_gemm<<<dim3(12,16),256>>>(wo, out, bo, 1, 3);
}

// round 14
// speedup vs baseline: 1.0959x; 1.0471x over previous
#include <cuda_runtime.h>

typedef unsigned long long u64;
#define DI static __device__ __forceinline__
DI u64 pk2(float lo, float hi){ u64 r; asm("mov.b64 %0,{%1,%2};":"=l"(r):"f"(lo),"f"(hi)); return r; }
DI void up2(u64 v, float&a, float&b){ asm("mov.b64 {%0,%1},%2;":"=f"(a),"=f"(b):"l"(v)); }
DI u64 fma2(u64 a,u64 b,u64 c){ u64 d; asm("fma.rn.f32x2 %0,%1,%2,%3;":"=l"(d):"l"(a),"l"(b),"l"(c)); return d; }
DI u64 mul2(u64 a,u64 b){ u64 d; asm("mul.rn.f32x2 %0,%1,%2;":"=l"(d):"l"(a),"l"(b)); return d; }
DI void cpasync16(unsigned s, const void* g){ asm volatile("cp.async.cg.shared.global [%0], [%1], 16;" :: "r"(s), "l"(g)); }
DI void cpcommit(){ asm volatile("cp.async.commit_group;"); }
DI void cpwait0(){ asm volatile("cp.async.wait_group 0;"); }
DI void cpwait1(){ asm volatile("cp.async.wait_group 1;"); }

#define SS 1024
#define CS 768
#define NH 24

__device__ __align__(16) float g_emb[2*3*CS];
__device__ __align__(16) float g_bsn[2*SS*CS];
__device__ __align__(16) float g_q[2*SS*CS];
__device__ __align__(16) float g_k[2*SS*CS];
__device__ __align__(16) float g_v[2*SS*CS];
__device__ __align__(16) float g_attno[2*SS*CS];
__device__ __align__(16) float g_bias[NH*SS*SS];
__device__ __align__(16) float g_wzpf[128*NH];
__device__ float g_colsum[NH];
__device__ float g_consth[NH];

__global__ void k_prep(const float* __restrict__ wz, const float* __restrict__ lnw,
                       const float* __restrict__ lnb){
    int t = threadIdx.x; // 128
    float w = lnw[t];
    #pragma unroll
    for(int h=0;h<NH;h++) g_wzpf[t*NH+h] = w*wz[t*NH+h];
    if(t < NH){
        float cs=0.f, ch=0.f;
        for(int c=0;c<128;c++){ cs += lnw[c]*wz[c*NH+t]; ch += lnb[c]*wz[c*NH+t]; }
        g_colsum[t]=cs; g_consth[t]=ch;
    }
}

__global__ void k_emb(const float* __restrict__ tin, const float* __restrict__ wad,
                      const float* __restrict__ bad){
    __shared__ float st[CS];
    int b = blockIdx.y;
    for(int i=threadIdx.x;i<CS;i+=256){ float v=tin[b*CS+i]; st[i]=v/(1.f+__expf(-v)); }
    __syncthreads();
    int j = blockIdx.x*256 + threadIdx.x;
    float acc = bad[j];
    #pragma unroll 8
    for(int i=0;i<CS;i++) acc = fmaf(st[i], wad[i*2304+j], acc);
    g_emb[b*2304+j] = acc;
}

__global__ void k_bsnorm(const float* __restrict__ bs){
    int row = blockIdx.x, b = row>>10;
    const float* x = bs + row*CS;
    __shared__ float red[16];
    float v[3]; float s=0.f, ss=0.f;
    #pragma unroll
    for(int i=0;i<3;i++){ v[i]=x[threadIdx.x+i*256]; s+=v[i]; ss=fmaf(v[i],v[i],ss); }
    #pragma unroll
    for(int m=16;m;m>>=1){ s+=__shfl_xor_sync(~0u,s,m); ss+=__shfl_xor_sync(~0u,ss,m); }
    if((threadIdx.x&31)==0){ red[threadIdx.x>>5]=s; red[8+(threadIdx.x>>5)]=ss; }
    __syncthreads();
    float S=0.f, SSm=0.f;
    #pragma unroll
    for(int i=0;i<8;i++){ S+=red[i]; SSm+=red[8+i]; }
    float mu = S*(1.f/768.f);
    float rs = rsqrtf(SSm*(1.f/768.f)-mu*mu + 1e-5f);
    #pragma unroll
    for(int i=0;i<3;i++){
        int c = threadIdx.x+i*256;
        g_bsn[row*CS+c] = (v[i]-mu)*rs*(1.f+g_emb[b*2304+768+c])+g_emb[b*2304+c];
    }
}

// ---- k_bias v5: 256 threads, 256 rows/block, 2 blocks/SM.
// warp owns 32 rows; lane rg=lane&7 owns rows rg+8j (j<4), hg=lane>>3 owns heads hg*6..+5.
#define ZSTR 36
#define BUFSZ (256*ZSTR)
extern __shared__ __align__(16) unsigned char dynsm[];

__global__ void __launch_bounds__(256,2) k_bias(const float* __restrict__ z,
                                                const int* __restrict__ zm){
    u64* swzp = (u64*)dynsm;                       // 128c x 4hg x 4 u64 = 16KB
    float* zbuf = (float*)(dynsm + 16384);         // 2 x 256 x 36 floats
    unsigned zshm = (unsigned)__cvta_generic_to_shared(zbuf);
    int t = threadIdx.x;
    long long p0 = (long long)blockIdx.x * 256;
    #pragma unroll
    for(int e=t; e<512; e+=256){
        int c = e>>2, hg = e&3;
        const float* w = g_wzpf + c*24 + hg*6;
        u64* dst = swzp + e*4;
        dst[0]=pk2(w[0],w[1]); dst[1]=pk2(w[2],w[3]); dst[2]=pk2(w[4],w[5]); dst[3]=0;
    }
    int lane = t&31, warp = t>>5;
    int rg = lane&7, hg = lane>>3;
    int rowBase = warp*32 + rg;

    u64 acc[4][3], st[4];
    #pragma unroll
    for(int j=0;j<4;j++){ acc[j][0]=0; acc[j][1]=0; acc[j][2]=0; st[j]=0; }

    {   // prefetch chunk 0 into buf 0
        const float* src = z + p0*128;
        #pragma unroll
        for(int i=0;i<8;i++){
            int li = t + 256*i; int r = li>>3, q = li&7;
            cpasync16(zshm + (r*ZSTR + q*4)*4, src + (long long)r*128 + q*4);
        }
        cpcommit();
    }
    for(int ch=0; ch<4; ch++){
        if(ch < 3){
            int b = (ch+1)&1;
            const float* src = z + p0*128 + (ch+1)*32;
            #pragma unroll
            for(int i=0;i<8;i++){
                int li = t + 256*i; int r = li>>3, q = li&7;
                cpasync16(zshm + (b*BUFSZ + r*ZSTR + q*4)*4, src + (long long)r*128 + q*4);
            }
            cpcommit();
            cpwait1();
        } else {
            cpwait0();
        }
        __syncthreads();
        const float* zb = zbuf + (ch&1)*BUFSZ + rowBase*ZSTR;
        #pragma unroll
        for(int c4=0;c4<8;c4++){
            float4 zf[4];
            #pragma unroll
            for(int j=0;j<4;j++) zf[j] = *(const float4*)(zb + j*8*ZSTR + c4*4);
            #pragma unroll
            for(int cc=0;cc<4;cc++){
                int c = ch*32 + c4*4 + cc;
                const u64* w = swzp + (c*4 + hg)*4;
                ulonglong2 wp = *(const ulonglong2*)w;
                u64 w2 = w[2];
                #pragma unroll
                for(int j=0;j<4;j++){
                    float zv = (cc==0)?zf[j].x : (cc==1)?zf[j].y : (cc==2)?zf[j].z : zf[j].w;
                    u64 zz = pk2(zv,zv);
                    acc[j][0]=fma2(zz,wp.x,acc[j][0]);
                    acc[j][1]=fma2(zz,wp.y,acc[j][1]);
                    acc[j][2]=fma2(zz,w2 ,acc[j][2]);
                    st[j]  =fma2(zz,pk2(1.f,zv),st[j]);   // (sum, sumsq)
                }
            }
        }
        __syncthreads();
    }
    float csl[6], chl[6];
    #pragma unroll
    for(int k=0;k<6;k++){ csl[k]=g_colsum[hg*6+k]; chl[k]=g_consth[hg*6+k]; }
    #pragma unroll
    for(int j=0;j<4;j++){
        long long p = p0 + rowBase + 8*j;
        float s, ss; up2(st[j], s, ss);
        float mu = s*(1.f/128.f);
        float rs = rsqrtf(ss*(1.f/128.f)-mu*mu + 1e-5f);
        float mb = (zm[p]>0) ? 0.f : -1e9f;
        #pragma unroll
        for(int k=0;k<3;k++){
            float d0,d1; up2(acc[j][k],d0,d1);
            int h0 = hg*6 + 2*k;
            g_bias[(long long)h0*1048576 + p]     = rs*(d0-mu*csl[2*k  ]) + chl[2*k  ] + mb;
            g_bias[(long long)(h0+1)*1048576 + p] = rs*(d1-mu*csl[2*k+1]) + chl[2*k+1] + mb;
        }
    }
}

// C[2048x768] = A @ W ; asel 0:g_bsn 1:g_attno ; csel 0..2 -> q/k/v (0/1 fuse RMS), 3 -> Cext (+b_o, *gate)
__global__ void __launch_bounds__(256) k_gemm(const float* __restrict__ W, float* __restrict__ Cext,
                                              const float* __restrict__ bo, const float* __restrict__ rmsw,
                                              float qs, int asel, int csel){
    __shared__ __align__(16) float as[16*130];
    __shared__ __align__(16) float bsm[16*64];
    const float* A = asel ? g_attno : g_bsn;
    float* C = (csel==0)?g_q : (csel==1)?g_k : (csel==2)?g_v : Cext;
    int t = threadIdx.x, tx = t&15, ty = t>>4;
    int m0 = blockIdx.y*128, n0 = blockIdx.x*64;
    u64 acc[8][2];
    #pragma unroll
    for(int r=0;r<8;r++){ acc[r][0]=0ull; acc[r][1]=0ull; }
    for(int k0=0;k0<768;k0+=16){
        __syncthreads();
        #pragma unroll
        for(int i=0;i<2;i++){
            int li = t + i*256; int m = li>>2, kq = li&3;
            float4 f = *(const float4*)(A + (m0+m)*768 + k0 + kq*4);
            as[(kq*4+0)*130+m]=f.x; as[(kq*4+1)*130+m]=f.y;
            as[(kq*4+2)*130+m]=f.z; as[(kq*4+3)*130+m]=f.w;
        }
        {   int k = t>>4, nq = t&15;
            *(float4*)(bsm + k*64 + nq*4) = *(const float4*)(W + (k0+k)*768 + n0 + nq*4);
        }
        __syncthreads();
        #pragma unroll
        for(int kk=0;kk<16;kk++){
            const float2* ap = (const float2*)(as + kk*130 + ty*8);
            ulonglong2 bb = *(const ulonglong2*)(bsm + kk*64 + tx*4);
            #pragma unroll
            for(int p=0;p<4;p++){
                float2 a2 = ap[p];
                u64 r0 = pk2(a2.x,a2.x), r1 = pk2(a2.y,a2.y);
                acc[2*p  ][0]=fma2(r0,bb.x,acc[2*p  ][0]); acc[2*p  ][1]=fma2(r0,bb.y,acc[2*p  ][1]);
                acc[2*p+1][0]=fma2(r1,bb.x,acc[2*p+1][0]); acc[2*p+1][1]=fma2(r1,bb.y,acc[2*p+1][1]);
            }
        }
    }
    float4 wv4 = make_float4(1.f,1.f,1.f,1.f);
    if(csel<=1) wv4 = *(const float4*)(rmsw + ((n0+tx*4)&31));
    #pragma unroll
    for(int r=0;r<8;r++){
        int m = m0 + ty*8 + r, n = n0 + tx*4;
        float o0,o1,o2,o3; up2(acc[r][0],o0,o1); up2(acc[r][1],o2,o3);
        if(csel==3){
            const float* g = g_emb + (m>>10)*2304 + 1536;
            o0=(o0+bo[n])*g[n]; o1=(o1+bo[n+1])*g[n+1]; o2=(o2+bo[n+2])*g[n+2]; o3=(o3+bo[n+3])*g[n+3];
        } else if(csel<=1){
            float ssq = o0*o0+o1*o1+o2*o2+o3*o3;
            ssq += __shfl_xor_sync(~0u,ssq,1);
            ssq += __shfl_xor_sync(~0u,ssq,2);
            ssq += __shfl_xor_sync(~0u,ssq,4);
            float rs = rsqrtf(ssq*(1.f/32.f)+1e-5f)*qs;
            o0*=rs*wv4.x; o1*=rs*wv4.y; o2*=rs*wv4.z; o3*=rs*wv4.w;
        }
        *(float4*)(C + m*768 + n) = make_float4(o0,o1,o2,o3);
    }
}

__global__ void __launch_bounds__(256) k_attn(const float* __restrict__ beta){
    __shared__ __align__(16) float Qs[64*34];
    __shared__ __align__(16) float Kt[32*68];
    __shared__ __align__(16) float Vt[32*68];
    __shared__ __align__(16) float Ps[64*68];
    int t=threadIdx.x, tx=t&15, ty=t>>4;
    int h=blockIdx.y, b=blockIdx.z, s0=blockIdx.x*64;
    const float* qb = g_q + (b*1024+s0)*768 + h*32;
    #pragma unroll
    for(int i=0;i<2;i++){
        int li=t+i*256, row=li>>3, e=li&7;
        float4 f = *(const float4*)(qb + row*768 + e*4);
        float2* d=(float2*)(Qs+row*34+e*4);
        d[0]=make_float2(f.x,f.y); d[1]=make_float2(f.z,f.w);
    }
    float m[4], l[4]; u64 acc[4][2];
    #pragma unroll
    for(int ii=0;ii<4;ii++){ m[ii]=-1e30f; l[ii]=0.f; acc[ii][0]=0ull; acc[ii][1]=0ull; }
    const float* bias_h = g_bias + (long long)h*1048576 + s0*1024;
    const float* beta_b = beta  + (long long)b*1048576 + s0*1024;
    for(int kt=0;kt<16;kt++){
        int j0=kt*64;
        u64 S2[4][2];
        #pragma unroll
        for(int ii=0;ii<4;ii++){
            int idx=(ty*4+ii)*1024 + j0 + tx*4;
            float4 bb = *(const float4*)(bias_h + idx);
            float4 be = *(const float4*)(beta_b + idx);
            S2[ii][0]=pk2(bb.x+be.x, bb.y+be.y);
            S2[ii][1]=pk2(bb.z+be.z, bb.w+be.w);
        }
        const float* kb = g_k + (b*1024+j0)*768 + h*32;
        const float* vb = g_v + (b*1024+j0)*768 + h*32;
        float4 kf[2], vf[2];
        #pragma unroll
        for(int i=0;i<2;i++){
            int li=t+i*256, row=li>>3, e=li&7;
            kf[i]=*(const float4*)(kb+row*768+e*4);
            vf[i]=*(const float4*)(vb+row*768+e*4);
        }
        __syncthreads();
        #pragma unroll
        for(int i=0;i<2;i++){
            int li=t+i*256, row=li>>3, e=li&7;
            Kt[(e*4+0)*68+row]=kf[i].x; Kt[(e*4+1)*68+row]=kf[i].y;
            Kt[(e*4+2)*68+row]=kf[i].z; Kt[(e*4+3)*68+row]=kf[i].w;
            Vt[(e*4+0)*68+row]=vf[i].x; Vt[(e*4+1)*68+row]=vf[i].y;
            Vt[(e*4+2)*68+row]=vf[i].z; Vt[(e*4+3)*68+row]=vf[i].w;
        }
        __syncthreads();
        #pragma unroll 8
        for(int d=0;d<32;d++){
            ulonglong2 kk = *(const ulonglong2*)(Kt + d*68 + tx*4);
            #pragma unroll
            for(int ii=0;ii<4;ii++){
                float qv = Qs[(ty*4+ii)*34+d];
                u64 qq = pk2(qv,qv);
                S2[ii][0]=fma2(qq,kk.x,S2[ii][0]);
                S2[ii][1]=fma2(qq,kk.y,S2[ii][1]);
            }
        }
        #pragma unroll
        for(int ii=0;ii<4;ii++){
            float sv0,sv1,sv2,sv3;
            up2(S2[ii][0],sv0,sv1); up2(S2[ii][1],sv2,sv3);
            float mx = fmaxf(fmaxf(sv0,sv1),fmaxf(sv2,sv3));
            #pragma unroll
            for(int w=1;w<16;w<<=1) mx = fmaxf(mx, __shfl_xor_sync(~0u,mx,w));
            float mn = fmaxf(m[ii], mx);
            float sc = __expf(m[ii]-mn);
            float p0=__expf(sv0-mn), p1=__expf(sv1-mn);
            float p2=__expf(sv2-mn), p3=__expf(sv3-mn);
            *(float4*)(Ps + (ty*4+ii)*68 + tx*4) = make_float4(p0,p1,p2,p3);
            float rs = p0+p1+p2+p3;
            #pragma unroll
            for(int w=1;w<16;w<<=1) rs += __shfl_xor_sync(~0u,rs,w);
            l[ii] = l[ii]*sc + rs; m[ii] = mn;
            u64 scp = pk2(sc,sc);
            acc[ii][0]=mul2(acc[ii][0],scp); acc[ii][1]=mul2(acc[ii][1],scp);
        }
        __syncthreads();
        #pragma unroll 4
        for(int j4=0;j4<64;j4+=4){
            ulonglong2 v0 = *(const ulonglong2*)(Vt + tx*68 + j4);
            ulonglong2 v1 = *(const ulonglong2*)(Vt + (tx+16)*68 + j4);
            #pragma unroll
            for(int ii=0;ii<4;ii++){
                ulonglong2 pp = *(const ulonglong2*)(Ps + (ty*4+ii)*68 + j4);
                acc[ii][0]=fma2(pp.x, v0.x, acc[ii][0]);
                acc[ii][0]=fma2(pp.y, v0.y, acc[ii][0]);
                acc[ii][1]=fma2(pp.x, v1.x, acc[ii][1]);
                acc[ii][1]=fma2(pp.y, v1.y, acc[ii][1]);
            }
        }
    }
    #pragma unroll
    for(int ii=0;ii<4;ii++){
        float inv = 1.f/l[ii];
        float a0,a1,b0,b1;
        up2(acc[ii][0],a0,a1); up2(acc[ii][1],b0,b1);
        float* o = g_attno + (b*1024+s0+ty*4+ii)*768 + h*32;
        o[tx]    = (a0+a1)*inv;
        o[tx+16] = (b0+b1)*inv;
    }
}

extern "C" void kernel_launch(void* const* d_in, const int* in_sizes, int n_in,
                              void* d_out, int out_size) {
    const float* bs   = (const float*)d_in[0];
    const float* z    = (const float*)d_in[1];
    const float* tt   = (const float*)d_in[2];
    const float* beta = (const float*)d_in[3];
    const int*   zm   = (const int*)  d_in[4];
    const float* wad  = (const float*)d_in[5];
    const float* bad  = (const float*)d_in[6];
    const float* lnzw = (const float*)d_in[7];
    const float* lnzb = (const float*)d_in[8];
    const float* wq   = (const float*)d_in[9];
    const float* wk   = (const float*)d_in[10];
    const float* wv   = (const float*)d_in[11];
    const float* wz   = (const float*)d_in[12];
    const float* rqw  = (const float*)d_in[13];
    const float* rkw  = (const float*)d_in[14];
    const float* wo   = (const float*)d_in[15];
    const float* bo   = (const float*)d_in[16];
    float* out = (float*)d_out;

    cudaFuncSetAttribute(k_bias, cudaFuncAttributeMaxDynamicSharedMemorySize, 16384 + 2*BUFSZ*4);

    k_prep<<<1,128>>>(wz, lnzw, lnzb);
    k_emb<<<dim3(9,2),256>>>(tt, wad, bad);
    k_bsnorm<<<2048,256>>>(bs);
    k_bias<<<4096,256, 16384 + 2*BUFSZ*4>>>(z, zm);
    k_gemm<<<dim3(12,16),256>>>(wq, nullptr, nullptr, rqw, 0.17677669529663687f, 0, 0);
    k_gemm<<<dim3(12,16),256>>>(wk, nullptr, nullptr, rkw, 1.f, 0, 1);
    k_gemm<<<dim3(12,16),256>>>(wv, nullptr, nullptr, nullptr, 1.f, 0, 2);
    k_attn<<<dim3(16,24,2),256>>>(beta);
    k_gemm<<<dim3(12,16),256>>>(wo, out, bo, nullptr, 1.f, 1, 3);
}